// round 5
// baseline (speedup 1.0000x reference)
#include <cuda_runtime.h>
#include <float.h>

#define BN 512
#define DN 256
#define NT 16            // 512 / 32 tiles per dim
#define NBLK 136         // NT*(NT+1)/2 upper-triangular tiles

// Scratch (no allocations allowed)
__device__ float g_pd[BN * BN];
__device__ float g_ploss[BN];
__device__ int   g_pcnt[BN];
__device__ unsigned int g_arrive;  // device-wide barrier counter (reset each call)
__device__ unsigned int g_done;    // mining-done counter (reset each call)

union SmemU {
    struct {
        float As[2][32][32];
        float Bs[2][32][32];
        float sq[2][32];
    } pd;
    struct {
        int   lab[BN];
        float row[4][BN];
    } mine;
};

// ---------------------------------------------------------------------------
// Single fused kernel:
//   Phase 1: symmetric pairwise sq-distance GEMM (136 upper-tri 32x32 tiles)
//   Phase 2: device-wide barrier (all 136 CTAs co-resident: 136 <= 148 SMs)
//   Phase 3: warp-per-anchor semi-hard mining (CTAs 0..127, 4 anchors each)
//   Phase 4: last-done CTA -> deterministic final reduction, counter reset
// ---------------------------------------------------------------------------
__global__ void __launch_bounds__(128) triplet_fused(const float* __restrict__ emb,
                                                     const int* __restrict__ labels,
                                                     float* __restrict__ out) {
    __shared__ SmemU sm;
    const int tid = threadIdx.x;
    const int lane = tid & 31, widx = tid >> 5;
    const unsigned FULL = 0xffffffffu;

    // ---- decode linear block -> (ti, tj), ti <= tj ----
    int b = blockIdx.x, ti = 0;
    while (b >= NT - ti) { b -= NT - ti; ti++; }
    const int tj = ti + b;
    const int i0 = ti * 32, j0 = tj * 32;

    // =========================== Phase 1: pd GEMM ===========================
    // norms: 2 threads per row, 64 rows (32 A + 32 B)
    {
        const int which = tid >> 6;
        const int r     = (tid >> 1) & 31;
        const int half  = tid & 1;
        const int row   = (which ? j0 : i0) + r;
        const float4* p = (const float4*)(emb + row * DN + half * 128);
        float s0 = 0.f, s1 = 0.f, s2 = 0.f, s3 = 0.f;
        #pragma unroll
        for (int i = 0; i < 32; i += 4) {
            float4 v;
            v = p[i + 0]; s0 = fmaf(v.x, v.x, fmaf(v.y, v.y, fmaf(v.z, v.z, fmaf(v.w, v.w, s0))));
            v = p[i + 1]; s1 = fmaf(v.x, v.x, fmaf(v.y, v.y, fmaf(v.z, v.z, fmaf(v.w, v.w, s1))));
            v = p[i + 2]; s2 = fmaf(v.x, v.x, fmaf(v.y, v.y, fmaf(v.z, v.z, fmaf(v.w, v.w, s2))));
            v = p[i + 3]; s3 = fmaf(v.x, v.x, fmaf(v.y, v.y, fmaf(v.z, v.z, fmaf(v.w, v.w, s3))));
        }
        float s = (s0 + s1) + (s2 + s3);
        s += __shfl_xor_sync(FULL, s, 1);
        if (!half) sm.pd.sq[which][r] = s;
    }

    // split-K x2 GEMM, 4x4 microtile
    {
        const int t  = tid & 63;
        const int g  = tid >> 6;
        const int lr = t >> 1;
        const int cq = (t & 1) * 4;
        const int ty = t >> 3;
        const int tx = t & 7;

        float acc[4][4] = {};
        const float* Arow = emb + (i0 + lr) * DN + g * 128;
        const float* Brow = emb + (j0 + lr) * DN + g * 128;

        for (int c0 = 0; c0 < 128; c0 += 32) {
            __syncthreads();
            #pragma unroll
            for (int e = 0; e < 4; e++) {
                float4 a4 = *(const float4*)(Arow + c0 + (cq + e) * 4);
                float4 b4 = *(const float4*)(Brow + c0 + (cq + e) * 4);
                const int kk = (cq + e) * 4;
                sm.pd.As[g][kk + 0][lr] = a4.x; sm.pd.As[g][kk + 1][lr] = a4.y;
                sm.pd.As[g][kk + 2][lr] = a4.z; sm.pd.As[g][kk + 3][lr] = a4.w;
                sm.pd.Bs[g][kk + 0][lr] = b4.x; sm.pd.Bs[g][kk + 1][lr] = b4.y;
                sm.pd.Bs[g][kk + 2][lr] = b4.z; sm.pd.Bs[g][kk + 3][lr] = b4.w;
            }
            __syncthreads();
            #pragma unroll
            for (int kk = 0; kk < 32; kk++) {
                float4 av = *(const float4*)&sm.pd.As[g][kk][ty << 2];
                float4 bv = *(const float4*)&sm.pd.Bs[g][kk][tx << 2];
                float ar[4] = {av.x, av.y, av.z, av.w};
                float br[4] = {bv.x, bv.y, bv.z, bv.w};
                #pragma unroll
                for (int u = 0; u < 4; u++)
                    #pragma unroll
                    for (int v = 0; v < 4; v++)
                        acc[u][v] = fmaf(ar[u], br[v], acc[u][v]);
            }
        }

        __syncthreads();
        if (g == 1) {
            float* dst = &sm.pd.As[0][0][0] + t * 16;
            #pragma unroll
            for (int u = 0; u < 4; u++)
                #pragma unroll
                for (int v = 0; v < 4; v++) dst[u * 4 + v] = acc[u][v];
        }
        __syncthreads();
        if (g == 0) {
            const float* src = &sm.pd.As[0][0][0] + t * 16;
            float d[4][4];
            #pragma unroll
            for (int u = 0; u < 4; u++) {
                const int gi = i0 + (ty << 2) + u;
                const float sqi = sm.pd.sq[0][(ty << 2) + u];
                #pragma unroll
                for (int v = 0; v < 4; v++) {
                    const int gj = j0 + (tx << 2) + v;
                    const float dot = acc[u][v] + src[u * 4 + v];
                    float val = fmaxf(sqi + sm.pd.sq[1][(tx << 2) + v] - 2.f * dot, 0.f);
                    if (gi == gj) val = 0.f;
                    d[u][v] = val;
                }
                *(float4*)(g_pd + gi * BN + j0 + (tx << 2)) =
                    make_float4(d[u][0], d[u][1], d[u][2], d[u][3]);
            }
            if (ti != tj) {
                #pragma unroll
                for (int v = 0; v < 4; v++) {
                    const int gj = j0 + (tx << 2) + v;
                    *(float4*)(g_pd + gj * BN + i0 + (ty << 2)) =
                        make_float4(d[0][v], d[1][v], d[2][v], d[3][v]);
                }
            }
        }
    }

    // ======================= Phase 2: device barrier ========================
    __syncthreads();
    if (tid == 0) {
        __threadfence();                       // publish g_pd writes
        atomicAdd(&g_arrive, 1u);
        while (*(volatile unsigned int*)&g_arrive < NBLK) { __nanosleep(32); }
    }
    __syncthreads();
    __threadfence();                           // acquire: g_pd visible to all

    // ========================= Phase 3: mining ==============================
    const int cb = blockIdx.x;
    if (cb < BN / 4) {
        // load labels into smem (pd smem now dead)
        for (int k = tid; k < BN; k += 128) sm.mine.lab[k] = labels[k];
        __syncthreads();

        const int j = cb * 4 + widx;           // anchor
        const int lj = sm.mine.lab[j];
        const float* rowp = g_pd + j * BN;

        float v[16];
        unsigned nmask = 0, pmask = 0;
        #pragma unroll
        for (int c = 0; c < 16; c++) {
            const int k = c * 32 + lane;
            v[c] = rowp[k];
            sm.mine.row[widx][k] = v[c];
            const bool same = (sm.mine.lab[k] == lj);
            if (!same) nmask |= (1u << c);
            if (same && k != j) pmask |= (1u << c);
        }

        float mx = -FLT_MAX, mn = FLT_MAX;
        #pragma unroll
        for (int c = 0; c < 16; c++) {
            if ((nmask >> c) & 1) mx = fmaxf(mx, v[c]);
            mn = fminf(mn, v[c]);
        }
        #pragma unroll
        for (int o = 16; o; o >>= 1) {
            mx = fmaxf(mx, __shfl_xor_sync(FULL, mx, o));
            mn = fminf(mn, __shfl_xor_sync(FULL, mn, o));
        }
        const float ninside = (mx > -FLT_MAX) ? mx : mn;

        float wsum = 0.f;
        int cnt = 0;
        int pend = -1;
        #pragma unroll 1
        for (int c = 0; c < 16; c++) {
            unsigned pm = __ballot_sync(FULL, (pmask >> c) & 1);
            while (pm) {
                const int bb = __ffs(pm) - 1;
                pm &= pm - 1;
                const int i = c * 32 + bb;
                cnt++;
                if (pend < 0) { pend = i; continue; }
                const float t1 = sm.mine.row[widx][pend];
                const float t2 = sm.mine.row[widx][i];
                float m1 = FLT_MAX, m2 = FLT_MAX;
                #pragma unroll
                for (int cc = 0; cc < 16; cc++) {
                    if ((nmask >> cc) & 1) {
                        const float x = v[cc];
                        if (x > t1) m1 = fminf(m1, x);
                        if (x > t2) m2 = fminf(m2, x);
                    }
                }
                #pragma unroll
                for (int o = 16; o; o >>= 1) {
                    m1 = fminf(m1, __shfl_xor_sync(FULL, m1, o));
                    m2 = fminf(m2, __shfl_xor_sync(FULL, m2, o));
                }
                const float semi1 = (m1 < FLT_MAX) ? m1 : ninside;
                const float semi2 = (m2 < FLT_MAX) ? m2 : ninside;
                wsum += fmaxf(1.0f + t1 - semi1, 0.f);
                wsum += fmaxf(1.0f + t2 - semi2, 0.f);
                pend = -1;
            }
        }
        if (pend >= 0) {
            const float t1 = sm.mine.row[widx][pend];
            float m1 = FLT_MAX;
            #pragma unroll
            for (int cc = 0; cc < 16; cc++) {
                if ((nmask >> cc) & 1) {
                    const float x = v[cc];
                    if (x > t1) m1 = fminf(m1, x);
                }
            }
            #pragma unroll
            for (int o = 16; o; o >>= 1)
                m1 = fminf(m1, __shfl_xor_sync(FULL, m1, o));
            const float semi1 = (m1 < FLT_MAX) ? m1 : ninside;
            wsum += fmaxf(1.0f + t1 - semi1, 0.f);
        }

        if (lane == 0) {
            g_ploss[j] = wsum;
            g_pcnt[j]  = cnt;
        }
        __syncthreads();
    }

    // ================= Phase 4: last CTA -> final reduction =================
    __shared__ int s_last;
    if (tid == 0) {
        __threadfence();
        const unsigned int vd = atomicAdd(&g_done, 1u);
        s_last = (vd == (unsigned)(NBLK - 1)) ? 1 : 0;
    }
    __syncthreads();

    if (s_last) {
        __threadfence();  // acquire
        float s = 0.f, c = 0.f;
        #pragma unroll
        for (int r = 0; r < 4; r++) {
            s += g_ploss[tid + r * 128];
            c += (float)g_pcnt[tid + r * 128];
        }
        #pragma unroll
        for (int o = 16; o; o >>= 1) {
            s += __shfl_xor_sync(FULL, s, o);
            c += __shfl_xor_sync(FULL, c, o);
        }
        __shared__ float ss[4], cc2[4];
        if (lane == 0) { ss[widx] = s; cc2[widx] = c; }
        __syncthreads();
        if (tid == 0) {
            float ts = 0.f, tc = 0.f;
            #pragma unroll
            for (int i = 0; i < 4; i++) { ts += ss[i]; tc += cc2[i]; }
            out[0] = ts / tc;
            g_arrive = 0;   // reset for next graph replay
            g_done   = 0;
        }
    }
}

// ---------------------------------------------------------------------------
extern "C" void kernel_launch(void* const* d_in, const int* in_sizes, int n_in,
                              void* d_out, int out_size) {
    const float* emb = (const float*)d_in[0];
    const int* labels = (const int*)d_in[1];
    float* out = (float*)d_out;

    triplet_fused<<<NBLK, 128>>>(emb, labels, out);
}